// round 1
// baseline (speedup 1.0000x reference)
#include <cuda_runtime.h>
#include <cuda_bf16.h>

#define N_NODES 10000
#define N_EDGES 64000
#define N_GRAPHS 64
#define HID 64
#define ET 128                    // edges per GEMM tile
#define NTILES (N_EDGES / ET)     // 500

// ---------------- scratch (device globals; no allocation allowed) ----------------
__device__ float g_h0[N_NODES * HID];
__device__ float g_h1[N_NODES * HID];
__device__ float g_agg[N_NODES * HID];
__device__ float g_tt[NTILES * HID * ET];   // edge-MLP output, tiled transposed: [tile][k][e]
__device__ float g_hst[NTILES * HID * ET];  // gathered h[src], tiled transposed: [tile][i][e]
__device__ int   g_src[N_EDGES];
__device__ int   g_dst[N_EDGES];
__device__ int   g_bat[N_NODES];
__device__ float g_hg[N_GRAPHS * HID];

__device__ __forceinline__ float lrelu(float v) { return v > 0.f ? v : 0.01f * v; }

// ---------------- cp.async helpers ----------------
__device__ __forceinline__ void cp16(float* s, const float* g) {
    unsigned sa = (unsigned)__cvta_generic_to_shared(s);
    asm volatile("cp.async.cg.shared.global [%0], [%1], 16;" :: "r"(sa), "l"(g));
}
__device__ __forceinline__ void cp_commit() { asm volatile("cp.async.commit_group;"); }

// ---------------- index conversion (int64-vs-int32 auto-detect) ----------------
__global__ void convert_idx_kernel(const void* ei, const void* bat) {
    __shared__ int s64;
    if (threadIdx.x == 0) {
        // edge_index values are random in [0,10000): if stored as int64, every odd
        // 32-bit word is 0; if int32, odd words are ~never 0. Same dtype applies to batch.
        const unsigned* w = (const unsigned*)ei;
        int z = 0;
        for (int i = 1; i < 256; i += 2) z += (w[i] == 0u);
        s64 = (z > 64);
    }
    __syncthreads();
    const bool is64 = (s64 != 0);
    int stride = blockDim.x * gridDim.x;
    for (int g = blockIdx.x * blockDim.x + threadIdx.x; g < N_EDGES; g += stride) {
        if (is64) {
            g_src[g] = (int)((const long long*)ei)[g];
            g_dst[g] = (int)((const long long*)ei)[N_EDGES + g];
        } else {
            g_src[g] = ((const int*)ei)[g];
            g_dst[g] = ((const int*)ei)[N_EDGES + g];
        }
    }
    for (int g = blockIdx.x * blockDim.x + threadIdx.x; g < N_NODES; g += stride) {
        g_bat[g] = is64 ? (int)((const long long*)bat)[g] : ((const int*)bat)[g];
    }
}

// ---------------- node encoder: h = lrelu(x @ W[128,64] + b) ----------------
__global__ void node_enc_kernel(const float* __restrict__ x, const float* __restrict__ w,
                                const float* __restrict__ b, float* __restrict__ h) {
    __shared__ float xs[16 * 128];
    __shared__ float ws[128 * 64];
    int tid = threadIdx.x;
    int n0 = blockIdx.x * 16;
    for (int idx = tid; idx < 16 * 128; idx += 256) xs[idx] = x[n0 * 128 + idx];
    for (int idx = tid; idx < 128 * 64; idx += 256) ws[idx] = w[idx];
    __syncthreads();
#pragma unroll
    for (int p = 0; p < 4; ++p) {
        int idx = p * 256 + tid;
        int o = idx & 63, nl = idx >> 6;
        float acc = b[o];
#pragma unroll 8
        for (int i = 0; i < 128; ++i) acc += xs[nl * 128 + i] * ws[i * 64 + o];
        h[n0 * 64 + idx] = lrelu(acc);
    }
}

// ---------------- edge MLP stage 1: t = relu(ea @ W1[32,64] + b1), written [tile][o][e] ----------------
__global__ void edge_mlp_kernel(const float* __restrict__ ea, const float* __restrict__ w1,
                                const float* __restrict__ b1, float* __restrict__ tt) {
    __shared__ float eas[128 * 33];
    __shared__ float w1s[32 * 64];
    __shared__ float b1s[64];
    int tid = threadIdx.x;
    int tile = blockIdx.x;
    for (int idx = tid; idx < 128 * 32; idx += 256) {
        int e = idx >> 5, j = idx & 31;
        eas[e * 33 + j] = ea[tile * 4096 + idx];
    }
    for (int idx = tid; idx < 2048; idx += 256) w1s[idx] = w1[idx];
    if (tid < 64) b1s[tid] = b1[tid];
    __syncthreads();
#pragma unroll 4
    for (int p = 0; p < 32; ++p) {
        int idx = p * 256 + tid;
        int e = idx & 127, o = idx >> 7;
        float acc = b1s[o];
#pragma unroll
        for (int j = 0; j < 32; ++j) acc += eas[e * 33 + j] * w1s[j * 64 + o];
        tt[tile * 8192 + o * 128 + e] = fmaxf(acc, 0.f);  // coalesced (e fastest)
    }
}

// ---------------- gather h[src] into tiled transposed layout [tile][i][e] ----------------
__global__ void gather_kernel(const float* __restrict__ h, float* __restrict__ hst) {
    int id = blockIdx.x * blockDim.x + threadIdx.x;  // < NTILES*HID*ET = 4,096,000
    int e_l = id & 127;
    int i = (id >> 7) & 63;
    int tile = id >> 13;
    int e = tile * ET + e_l;
    hst[id] = h[g_src[e] * HID + i];
}

__global__ void zero_kernel(float* p, int n) {
    int id = blockIdx.x * blockDim.x + threadIdx.x;
    if (id < n) p[id] = 0.f;
}

// ---------------- fused message GEMM + scatter ----------------
// msg[e,o] = sum_k t[e,k] * (sum_i hs[e,i]*w2[k][i*64+o])  +  sum_i hs[e,i]*b2[i*64+o]
// One CTA = 128 edges x 64 outputs. K-loop over 65 slices (64 w2-rows + b2).
__global__ void __launch_bounds__(128) msg_gemm_kernel(
    const float* __restrict__ tt, const float* __restrict__ hst,
    const float* __restrict__ w2, const float* __restrict__ b2,
    float* __restrict__ agg) {
    extern __shared__ float smp[];
    float* Hs = smp;               // [64][128]  h_src tile, i-major
    float* Ts = smp + 8192;        // [64][128]  t tile, k-major
    float* Bs = smp + 16384;       // [2][64][64] double-buffered w2 slice
    const int tid = threadIdx.x;
    const int tile = blockIdx.x;
    const int te = tid & 15;       // edge-octet index (e = te*8 + j)
    const int to = tid >> 4;       // output-octet index (o = to*8 + l)

    // stage 0: load Hs, Ts, B0
    {
        const float* hsrc = hst + tile * 8192;
        const float* tsrc = tt + tile * 8192;
#pragma unroll
        for (int q = 0; q < 16; ++q) {
            int f = (tid + q * 128) * 4;
            cp16(Hs + f, hsrc + f);
            cp16(Ts + f, tsrc + f);
        }
#pragma unroll
        for (int q = 0; q < 8; ++q) {
            int f = (tid + q * 128) * 4;
            cp16(Bs + f, w2 + f);
        }
        cp_commit();
    }

    float C[8][8];
#pragma unroll
    for (int j = 0; j < 8; ++j)
#pragma unroll
        for (int l = 0; l < 8; ++l) C[j][l] = 0.f;

    for (int k = 0; k <= 64; ++k) {
        if (k < 64) {
            const float* bsrc = (k + 1 < 64) ? (w2 + (k + 1) * 4096) : b2;
            float* bdst = Bs + ((k + 1) & 1) * 4096;
#pragma unroll
            for (int q = 0; q < 8; ++q) {
                int f = (tid + q * 128) * 4;
                cp16(bdst + f, bsrc + f);
            }
            cp_commit();
            asm volatile("cp.async.wait_group 1;");
        } else {
            asm volatile("cp.async.wait_group 0;");
        }
        __syncthreads();

        const float4* B4 = (const float4*)(Bs + (k & 1) * 4096);
        const float4* H4 = (const float4*)Hs;
        float tk[8];
        if (k < 64) {
            float4 t0 = ((const float4*)Ts)[k * 32 + te * 2];
            float4 t1 = ((const float4*)Ts)[k * 32 + te * 2 + 1];
            tk[0] = t0.x; tk[1] = t0.y; tk[2] = t0.z; tk[3] = t0.w;
            tk[4] = t1.x; tk[5] = t1.y; tk[6] = t1.z; tk[7] = t1.w;
        } else {
#pragma unroll
            for (int j = 0; j < 8; ++j) tk[j] = 1.f;  // bias slice
        }

        float P[8][8];
#pragma unroll
        for (int j = 0; j < 8; ++j)
#pragma unroll
            for (int l = 0; l < 8; ++l) P[j][l] = 0.f;

#pragma unroll 4
        for (int i = 0; i < 64; ++i) {
            float4 a0 = H4[i * 32 + te * 2];
            float4 a1 = H4[i * 32 + te * 2 + 1];
            float4 b0 = B4[i * 16 + to * 2];
            float4 b1 = B4[i * 16 + to * 2 + 1];
            float a[8] = {a0.x, a0.y, a0.z, a0.w, a1.x, a1.y, a1.z, a1.w};
            float b[8] = {b0.x, b0.y, b0.z, b0.w, b1.x, b1.y, b1.z, b1.w};
#pragma unroll
            for (int j = 0; j < 8; ++j)
#pragma unroll
                for (int l = 0; l < 8; ++l) P[j][l] += a[j] * b[l];
        }
#pragma unroll
        for (int j = 0; j < 8; ++j)
#pragma unroll
            for (int l = 0; l < 8; ++l) C[j][l] += tk[j] * P[j][l];
        __syncthreads();
    }

    // epilogue: scatter-add messages to destination nodes
    int e0 = tile * ET + te * 8;
#pragma unroll
    for (int j = 0; j < 8; ++j) {
        int d = g_dst[e0 + j];
        float* ap = agg + d * HID + to * 8;
#pragma unroll
        for (int l = 0; l < 8; ++l) atomicAdd(ap + l, C[j][l]);
    }
}

// ---------------- node update: h_out = lrelu(agg + h_in @ root + bias) ----------------
__global__ void node_update_kernel(const float* __restrict__ hin, const float* __restrict__ agg,
                                   const float* __restrict__ root, const float* __restrict__ bias,
                                   float* __restrict__ hout) {
    int id = blockIdx.x * blockDim.x + threadIdx.x;  // < 640000
    int n = id >> 6, o = id & 63;
    float acc = bias[o] + agg[id];
    const float* hr = hin + n * 64;
#pragma unroll 8
    for (int i = 0; i < 64; ++i) acc += hr[i] * root[i * 64 + o];
    hout[id] = lrelu(acc);
}

// ---------------- global add pool ----------------
__global__ void pool_kernel(const float* __restrict__ h) {
    int id = blockIdx.x * blockDim.x + threadIdx.x;  // < 640000
    int n = id >> 6, o = id & 63;
    atomicAdd(&g_hg[g_bat[n] * 64 + o], h[id]);
}

// ---------------- readout head ----------------
__global__ void head_kernel(const float* __restrict__ fc1w, const float* __restrict__ fc1b,
                            const float* __restrict__ fc2w, const float* __restrict__ fc2b,
                            float* __restrict__ out) {
    __shared__ float hs[N_GRAPHS * HID];
    int g = threadIdx.x;  // 64 threads
    for (int i = g; i < N_GRAPHS * HID; i += 64) hs[i] = g_hg[i];
    __syncthreads();
    float acc = fc2b[0];
#pragma unroll 4
    for (int j = 0; j < 32; ++j) {
        float s = fc1b[j];
#pragma unroll 8
        for (int i = 0; i < 64; ++i) s += hs[g * 64 + i] * fc1w[i * 32 + j];
        acc += lrelu(s) * fc2w[j];
    }
    out[g] = acc;
}

// ---------------- launch ----------------
extern "C" void kernel_launch(void* const* d_in, const int* in_sizes, int n_in,
                              void* d_out, int out_size) {
    const float* x     = (const float*)d_in[0];
    const void*  ei    = d_in[1];
    const float* ea    = (const float*)d_in[2];
    const void*  bat   = d_in[3];
    const float* nfc_w = (const float*)d_in[4];
    const float* nfc_b = (const float*)d_in[5];
    const float* e1w1  = (const float*)d_in[6];
    const float* e1b1  = (const float*)d_in[7];
    const float* e1w2  = (const float*)d_in[8];
    const float* e1b2  = (const float*)d_in[9];
    const float* root1 = (const float*)d_in[10];
    const float* bias1 = (const float*)d_in[11];
    const float* e2w1  = (const float*)d_in[12];
    const float* e2b1  = (const float*)d_in[13];
    const float* e2w2  = (const float*)d_in[14];
    const float* e2b2  = (const float*)d_in[15];
    const float* root2 = (const float*)d_in[16];
    const float* bias2 = (const float*)d_in[17];
    const float* fc1w  = (const float*)d_in[18];
    const float* fc1b  = (const float*)d_in[19];
    const float* fc2w  = (const float*)d_in[20];
    const float* fc2b  = (const float*)d_in[21];
    float* out = (float*)d_out;

    float *h0, *h1, *agg, *tt, *hst, *hg;
    cudaGetSymbolAddress((void**)&h0, g_h0);
    cudaGetSymbolAddress((void**)&h1, g_h1);
    cudaGetSymbolAddress((void**)&agg, g_agg);
    cudaGetSymbolAddress((void**)&tt, g_tt);
    cudaGetSymbolAddress((void**)&hst, g_hst);
    cudaGetSymbolAddress((void**)&hg, g_hg);

    cudaFuncSetAttribute(msg_gemm_kernel, cudaFuncAttributeMaxDynamicSharedMemorySize, 98304);

    convert_idx_kernel<<<256, 256>>>(ei, bat);
    node_enc_kernel<<<N_NODES / 16, 256>>>(x, nfc_w, nfc_b, h0);

    // layer 1
    edge_mlp_kernel<<<NTILES, 256>>>(ea, e1w1, e1b1, tt);
    gather_kernel<<<NTILES * HID * ET / 256, 256>>>(h0, hst);
    zero_kernel<<<(N_NODES * HID + 255) / 256, 256>>>(agg, N_NODES * HID);
    msg_gemm_kernel<<<NTILES, 128, 98304>>>(tt, hst, e1w2, e1b2, agg);
    node_update_kernel<<<(N_NODES * HID + 255) / 256, 256>>>(h0, agg, root1, bias1, h1);

    // layer 2
    edge_mlp_kernel<<<NTILES, 256>>>(ea, e2w1, e2b1, tt);
    gather_kernel<<<NTILES * HID * ET / 256, 256>>>(h1, hst);
    zero_kernel<<<(N_NODES * HID + 255) / 256, 256>>>(agg, N_NODES * HID);
    msg_gemm_kernel<<<NTILES, 128, 98304>>>(tt, hst, e2w2, e2b2, agg);
    node_update_kernel<<<(N_NODES * HID + 255) / 256, 256>>>(h1, agg, root2, bias2, h0);

    // pool + head
    zero_kernel<<<(N_GRAPHS * HID + 255) / 256, 256>>>(hg, N_GRAPHS * HID);
    pool_kernel<<<(N_NODES * HID + 255) / 256, 256>>>(h0);
    head_kernel<<<1, 64>>>(fc1w, fc1b, fc2w, fc2b, out);
}

// round 3
// speedup vs baseline: 3.0233x; 3.0233x over previous
#include <cuda_runtime.h>
#include <cuda_bf16.h>
#include <cstdint>

#define N_NODES 10000
#define N_EDGES 64000
#define N_GRAPHS 64
#define HID 64
#define ET 128                    // edges per GEMM tile
#define NTILES (N_EDGES / ET)     // 500
#define NSLICE 65                 // 64 w2 slices + 1 bias slice
#define BPAD 72                   // padded B row stride (floats), conflict-free
#define BSLICE (HID * BPAD)       // 4608 floats per prepped slice

// ---------------- scratch (device globals; no allocation allowed) ----------------
__device__ float g_h0[N_NODES * HID];
__device__ float g_h1[N_NODES * HID];
__device__ float g_agg[N_NODES * HID];
__device__ float g_tt[NTILES * HID * ET];     // edge-MLP output: [tile][k][e]
__device__ float g_hst[N_EDGES * HID];        // gathered h[src]: [e][i]
__device__ float g_bprep[NSLICE * BSLICE];    // w2 (+bias) tf32-rounded, padded [s][i][o]
__device__ int   g_src[N_EDGES];
__device__ int   g_dst[N_EDGES];
__device__ int   g_bat[N_NODES];
__device__ float g_hg[N_GRAPHS * HID];

__device__ __forceinline__ float lrelu(float v) { return v > 0.f ? v : 0.01f * v; }

// ---------------- PTX helpers ----------------
__device__ __forceinline__ void cp16(void* s, const void* g) {
    unsigned sa = (unsigned)__cvta_generic_to_shared(s);
    asm volatile("cp.async.cg.shared.global [%0], [%1], 16;" :: "r"(sa), "l"(g));
}
__device__ __forceinline__ void cp_commit() { asm volatile("cp.async.commit_group;"); }

__device__ __forceinline__ uint32_t tf32rn(float x) {
    uint32_t r;
    asm("cvt.rna.tf32.f32 %0, %1;" : "=r"(r) : "f"(x));
    return r;
}

__device__ __forceinline__ void mma8(float* c, const uint32_t* a, uint32_t b0, uint32_t b1) {
    asm volatile(
        "mma.sync.aligned.m16n8k8.row.col.f32.tf32.tf32.f32 "
        "{%0,%1,%2,%3}, {%4,%5,%6,%7}, {%8,%9}, {%0,%1,%2,%3};"
        : "+f"(c[0]), "+f"(c[1]), "+f"(c[2]), "+f"(c[3])
        : "r"(a[0]), "r"(a[1]), "r"(a[2]), "r"(a[3]), "r"(b0), "r"(b1));
}

// ---------------- index conversion (int64-vs-int32 auto-detect) ----------------
__global__ void convert_idx_kernel(const void* ei, const void* bat) {
    __shared__ int s64;
    if (threadIdx.x == 0) {
        const unsigned* w = (const unsigned*)ei;
        int z = 0;
        for (int i = 1; i < 256; i += 2) z += (w[i] == 0u);
        s64 = (z > 64);
    }
    __syncthreads();
    const bool is64 = (s64 != 0);
    int stride = blockDim.x * gridDim.x;
    for (int g = blockIdx.x * blockDim.x + threadIdx.x; g < N_EDGES; g += stride) {
        if (is64) {
            g_src[g] = (int)((const long long*)ei)[g];
            g_dst[g] = (int)((const long long*)ei)[N_EDGES + g];
        } else {
            g_src[g] = ((const int*)ei)[g];
            g_dst[g] = ((const int*)ei)[N_EDGES + g];
        }
    }
    for (int g = blockIdx.x * blockDim.x + threadIdx.x; g < N_NODES; g += stride) {
        g_bat[g] = is64 ? (int)((const long long*)bat)[g] : ((const int*)bat)[g];
    }
}

// ---------------- node encoder: h = lrelu(x @ W[128,64] + b) ----------------
__global__ void node_enc_kernel(const float* __restrict__ x, const float* __restrict__ w,
                                const float* __restrict__ b, float* __restrict__ h) {
    __shared__ float xs[16 * 128];
    __shared__ float ws[128 * 64];
    int tid = threadIdx.x;
    int n0 = blockIdx.x * 16;
    for (int idx = tid; idx < 16 * 128; idx += 256) xs[idx] = x[n0 * 128 + idx];
    for (int idx = tid; idx < 128 * 64; idx += 256) ws[idx] = w[idx];
    __syncthreads();
#pragma unroll
    for (int p = 0; p < 4; ++p) {
        int idx = p * 256 + tid;
        int o = idx & 63, nl = idx >> 6;
        float acc = b[o];
#pragma unroll 8
        for (int i = 0; i < 128; ++i) acc += xs[nl * 128 + i] * ws[i * 64 + o];
        h[n0 * 64 + idx] = lrelu(acc);
    }
}

// ---------------- edge MLP stage 1: t = relu(ea @ W1[32,64] + b1) -> [tile][k][e] ----------------
__global__ void edge_mlp_kernel(const float* __restrict__ ea, const float* __restrict__ w1,
                                const float* __restrict__ b1, float* __restrict__ tt) {
    __shared__ float eas[128 * 33];
    __shared__ float w1s[32 * 64];
    __shared__ float b1s[64];
    int tid = threadIdx.x;
    int tile = blockIdx.x;
    for (int idx = tid; idx < 128 * 32; idx += 256) {
        int e = idx >> 5, j = idx & 31;
        eas[e * 33 + j] = ea[tile * 4096 + idx];
    }
    for (int idx = tid; idx < 2048; idx += 256) w1s[idx] = w1[idx];
    if (tid < 64) b1s[tid] = b1[tid];
    __syncthreads();
#pragma unroll 4
    for (int p = 0; p < 32; ++p) {
        int idx = p * 256 + tid;
        int e = idx & 127, o = idx >> 7;
        float acc = b1s[o];
#pragma unroll
        for (int j = 0; j < 32; ++j) acc += eas[e * 33 + j] * w1s[j * 64 + o];
        tt[tile * 8192 + o * 128 + e] = fmaxf(acc, 0.f);
    }
}

// ---------------- gather h[src] into e-major layout [e][i] ----------------
__global__ void gather_kernel(const float* __restrict__ h, float* __restrict__ hst) {
    int id = blockIdx.x * blockDim.x + threadIdx.x;  // < N_EDGES*HID
    int i = id & 63;
    int e = id >> 6;
    hst[id] = h[g_src[e] * HID + i];
}

__global__ void zero_kernel(float* p, int n) {
    int id = blockIdx.x * blockDim.x + threadIdx.x;
    if (id < n) p[id] = 0.f;
}

// ---------------- B prep: tf32-round w2 (+b2) into padded [s][i][o] (stride BPAD) ----------------
__global__ void bprep_kernel(const float* __restrict__ w2, const float* __restrict__ b2,
                             uint32_t* __restrict__ bp) {
    int id = blockIdx.x * blockDim.x + threadIdx.x;  // < 65*4096
    if (id >= NSLICE * 4096) return;
    int s = id >> 12;
    int r = id & 4095;
    int i = r >> 6, o = r & 63;
    float v = (s < 64) ? w2[(s << 12) + (i << 6) + o] : b2[(i << 6) + o];
    bp[s * BSLICE + i * BPAD + o] = tf32rn(v);
}

// ---------------- tf32 mma.sync message GEMM + scatter ----------------
// C[128 e, 64 o] = sum_{k<65} diag(t_k) * H[128,64] @ B_k[64,64]   (t_64 = 1, B_64 = bias)
__global__ void __launch_bounds__(128, 3) msg_mma_kernel(
    const float* __restrict__ tt, const float* __restrict__ hst,
    const uint32_t* __restrict__ bp, float* __restrict__ agg) {
    __shared__ uint32_t Bs[2][BSLICE];
    const int tid = threadIdx.x;
    const int w = tid >> 5, lane = tid & 31;
    const int g = lane >> 2, tig = lane & 3;
    const int tile = blockIdx.x;

    // prefetch B slice 0 (group 0)
    {
        const uint32_t* s = bp;
#pragma unroll
        for (int q = 0; q < 9; ++q) {
            int f = (tid + q * 128) * 4;
            cp16(&Bs[0][f], s + f);
        }
        cp_commit();
    }

    // H tile registers: h[m][r][kt*2+c] = H[w*32 + m*16 + r*8 + g][kt*8 + c*4 + tig]
    float h[2][2][16];
    {
        const float* hb = hst + ((size_t)tile * 128 + w * 32 + g) * 64;
#pragma unroll
        for (int m = 0; m < 2; ++m)
#pragma unroll
            for (int r = 0; r < 2; ++r) {
                const float* hp = hb + (m * 16 + r * 8) * 64 + tig;
#pragma unroll
                for (int kt = 0; kt < 8; ++kt) {
                    h[m][r][kt * 2 + 0] = hp[kt * 8];
                    h[m][r][kt * 2 + 1] = hp[kt * 8 + 4];
                }
            }
    }

    float C[2][8][4];
#pragma unroll
    for (int m = 0; m < 2; ++m)
#pragma unroll
        for (int nt = 0; nt < 8; ++nt)
#pragma unroll
            for (int q = 0; q < 4; ++q) C[m][nt][q] = 0.f;

    const float* tbase = tt + (size_t)tile * 8192 + w * 32 + g;

    for (int k = 0; k < NSLICE; ++k) {
        const int b = k & 1;
        if (k < NSLICE - 1) {
            const uint32_t* s = bp + (size_t)(k + 1) * BSLICE;
            uint32_t* d = Bs[b ^ 1];
#pragma unroll
            for (int q = 0; q < 9; ++q) {
                int f = (tid + q * 128) * 4;
                cp16(d + f, s + f);
            }
            cp_commit();
            asm volatile("cp.async.wait_group 1;");
        } else {
            asm volatile("cp.async.wait_group 0;");
        }
        __syncthreads();

        float tk[4];
        if (k < 64) {
            const float* tp = tbase + k * 128;
            tk[0] = tp[0]; tk[1] = tp[8]; tk[2] = tp[16]; tk[3] = tp[24];
        } else {
            tk[0] = tk[1] = tk[2] = tk[3] = 1.f;
        }

        const uint32_t* B = Bs[b];
#pragma unroll
        for (int kt = 0; kt < 8; ++kt) {
            uint32_t a[2][4];
#pragma unroll
            for (int m = 0; m < 2; ++m) {
                a[m][0] = tf32rn(h[m][0][kt * 2 + 0] * tk[2 * m + 0]);
                a[m][1] = tf32rn(h[m][1][kt * 2 + 0] * tk[2 * m + 1]);
                a[m][2] = tf32rn(h[m][0][kt * 2 + 1] * tk[2 * m + 0]);
                a[m][3] = tf32rn(h[m][1][kt * 2 + 1] * tk[2 * m + 1]);
            }
            const uint32_t* Brow = B + (kt * 8 + tig) * BPAD + g;
#pragma unroll
            for (int nt = 0; nt < 8; ++nt) {
                uint32_t b0 = Brow[nt * 8];
                uint32_t b1 = Brow[nt * 8 + 4 * BPAD];
                mma8(C[0][nt], a[0], b0, b1);
                mma8(C[1][nt], a[1], b0, b1);
            }
        }
        __syncthreads();
    }

    // epilogue: scatter-add to agg[dst]
    const int ebase = tile * 128 + w * 32 + g;
#pragma unroll
    for (int m = 0; m < 2; ++m) {
        int d0 = g_dst[ebase + m * 16];
        int d1 = g_dst[ebase + m * 16 + 8];
        float* p0 = agg + (size_t)d0 * 64 + 2 * tig;
        float* p1 = agg + (size_t)d1 * 64 + 2 * tig;
#pragma unroll
        for (int nt = 0; nt < 8; ++nt) {
            atomicAdd(p0 + nt * 8 + 0, C[m][nt][0]);
            atomicAdd(p0 + nt * 8 + 1, C[m][nt][1]);
            atomicAdd(p1 + nt * 8 + 0, C[m][nt][2]);
            atomicAdd(p1 + nt * 8 + 1, C[m][nt][3]);
        }
    }
}

// ---------------- node update: h_out = lrelu(agg + h_in @ root + bias) ----------------
__global__ void node_update_kernel(const float* __restrict__ hin, const float* __restrict__ agg,
                                   const float* __restrict__ root, const float* __restrict__ bias,
                                   float* __restrict__ hout) {
    int id = blockIdx.x * blockDim.x + threadIdx.x;
    int n = id >> 6, o = id & 63;
    float acc = bias[o] + agg[id];
    const float* hr = hin + n * 64;
#pragma unroll 8
    for (int i = 0; i < 64; ++i) acc += hr[i] * root[i * 64 + o];
    hout[id] = lrelu(acc);
}

// ---------------- global add pool ----------------
__global__ void pool_kernel(const float* __restrict__ h) {
    int id = blockIdx.x * blockDim.x + threadIdx.x;
    int n = id >> 6, o = id & 63;
    atomicAdd(&g_hg[g_bat[n] * 64 + o], h[id]);
}

// ---------------- readout head ----------------
__global__ void head_kernel(const float* __restrict__ fc1w, const float* __restrict__ fc1b,
                            const float* __restrict__ fc2w, const float* __restrict__ fc2b,
                            float* __restrict__ out) {
    __shared__ float hs[N_GRAPHS * HID];
    int g = threadIdx.x;
    for (int i = g; i < N_GRAPHS * HID; i += 64) hs[i] = g_hg[i];
    __syncthreads();
    float acc = fc2b[0];
#pragma unroll 4
    for (int j = 0; j < 32; ++j) {
        float s = fc1b[j];
#pragma unroll 8
        for (int i = 0; i < 64; ++i) s += hs[g * 64 + i] * fc1w[i * 32 + j];
        acc += lrelu(s) * fc2w[j];
    }
    out[g] = acc;
}

// ---------------- launch ----------------
extern "C" void kernel_launch(void* const* d_in, const int* in_sizes, int n_in,
                              void* d_out, int out_size) {
    const float* x     = (const float*)d_in[0];
    const void*  ei    = d_in[1];
    const float* ea    = (const float*)d_in[2];
    const void*  bat   = d_in[3];
    const float* nfc_w = (const float*)d_in[4];
    const float* nfc_b = (const float*)d_in[5];
    const float* e1w1  = (const float*)d_in[6];
    const float* e1b1  = (const float*)d_in[7];
    const float* e1w2  = (const float*)d_in[8];
    const float* e1b2  = (const float*)d_in[9];
    const float* root1 = (const float*)d_in[10];
    const float* bias1 = (const float*)d_in[11];
    const float* e2w1  = (const float*)d_in[12];
    const float* e2b1  = (const float*)d_in[13];
    const float* e2w2  = (const float*)d_in[14];
    const float* e2b2  = (const float*)d_in[15];
    const float* root2 = (const float*)d_in[16];
    const float* bias2 = (const float*)d_in[17];
    const float* fc1w  = (const float*)d_in[18];
    const float* fc1b  = (const float*)d_in[19];
    const float* fc2w  = (const float*)d_in[20];
    const float* fc2b  = (const float*)d_in[21];
    float* out = (float*)d_out;

    float *h0, *h1, *agg, *tt, *hst, *hg;
    uint32_t* bpp;
    cudaGetSymbolAddress((void**)&h0, g_h0);
    cudaGetSymbolAddress((void**)&h1, g_h1);
    cudaGetSymbolAddress((void**)&agg, g_agg);
    cudaGetSymbolAddress((void**)&tt, g_tt);
    cudaGetSymbolAddress((void**)&hst, g_hst);
    cudaGetSymbolAddress((void**)&hg, g_hg);
    cudaGetSymbolAddress((void**)&bpp, g_bprep);

    convert_idx_kernel<<<256, 256>>>(ei, bat);
    node_enc_kernel<<<N_NODES / 16, 256>>>(x, nfc_w, nfc_b, h0);

    // layer 1
    bprep_kernel<<<(NSLICE * 4096 + 255) / 256, 256>>>(e1w2, e1b2, bpp);
    edge_mlp_kernel<<<NTILES, 256>>>(ea, e1w1, e1b1, tt);
    gather_kernel<<<N_EDGES * HID / 256, 256>>>(h0, hst);
    zero_kernel<<<(N_NODES * HID + 255) / 256, 256>>>(agg, N_NODES * HID);
    msg_mma_kernel<<<NTILES, 128>>>(tt, hst, bpp, agg);
    node_update_kernel<<<(N_NODES * HID + 255) / 256, 256>>>(h0, agg, root1, bias1, h1);

    // layer 2
    bprep_kernel<<<(NSLICE * 4096 + 255) / 256, 256>>>(e2w2, e2b2, bpp);
    edge_mlp_kernel<<<NTILES, 256>>>(ea, e2w1, e2b1, tt);
    gather_kernel<<<N_EDGES * HID / 256, 256>>>(h1, hst);
    zero_kernel<<<(N_NODES * HID + 255) / 256, 256>>>(agg, N_NODES * HID);
    msg_mma_kernel<<<NTILES, 128>>>(tt, hst, bpp, agg);
    node_update_kernel<<<(N_NODES * HID + 255) / 256, 256>>>(h1, agg, root2, bias2, h0);

    // pool + head
    zero_kernel<<<(N_GRAPHS * HID + 255) / 256, 256>>>(hg, N_GRAPHS * HID);
    pool_kernel<<<(N_NODES * HID + 255) / 256, 256>>>(h0);
    head_kernel<<<1, 64>>>(fc1w, fc1b, fc2w, fc2b, out);
}